// round 7
// baseline (speedup 1.0000x reference)
#include <cuda_runtime.h>

// Abbott STDP step, fused single kernel. D=8, B=2, N=2048.
// Out = concat(W_prev[B,N,N], W_new[B,N,N], xbar_pre_new[D,B,N], xbar_post_new[B,N])
//
// Measured structure notes (do not regress):
//  - Load dmap INSIDE the d-loop, consume immediately (front-loading dm[8]
//    cost +3.8us in R4). Persistent blocks w/ barriers cost -7% DRAM (R3).
//  - Warp-shfl broadcast of per-row scalars, no smem/syncthreads (R5 win).
//  - R6: registers were the occupancy cap (63 regs -> 2 blocks/SM).
//    Refactor dW = sum_d dm*(u*p - t*v) with u=A_p*Xpost, t=A_d*xbar_post
//    halves accumulator count; launch_bounds(512,3) -> 48 warps/SM.

#define DD 8
#define BB 2
#define NN 2048
#define ALPHA_P 0.95f
#define ALPHA_D 0.90f

static const long long N2  = (long long)NN * NN;       // 4,194,304
static const long long BN2 = (long long)BB * N2;       // 8,388,608
static const long long DBN = (long long)DD * BB * NN;  // 32,768
static const long long BN  = (long long)BB * NN;       // 4,096

__global__ __launch_bounds__(512, 3) void stdp_fused(
    const float* __restrict__ Xd,        // (D,B,N)
    const float* __restrict__ Xpost,     // (B,N)
    const float* __restrict__ xbar_pre,  // (D,B,N)
    const float* __restrict__ xbar_post, // (B,N)
    const float* __restrict__ W,         // (B,N,N)
    const float* __restrict__ dmap,      // (D,N,N)
    const float* __restrict__ A_p,       // (N,N)
    const float* __restrict__ A_d,       // (N,N)
    float* __restrict__ W_prev_out,
    float* __restrict__ W_new_out,
    float* __restrict__ pre_out,         // (D,B,N) or nullptr
    float* __restrict__ post_out)        // (B,N)   or nullptr
{
    const int e    = blockIdx.x;
    const int lane = threadIdx.x & 31;

    // Warp-local broadcast of the 2*D*B=32 per-row scalars:
    // lane l<16 holds xbar_pre[l*NN+e] (l = d*BB+b); lane l>=16 holds Xd.
    const float* sbase = (lane < 16) ? xbar_pre : Xd;
    const float v = __ldg(sbase + (size_t)(lane & 15) * NN + e);

    // Fused pre-trace output: warp 0, lanes 0..15 (one value each).
    const float vpartner = __shfl_xor_sync(0xffffffffu, v, 16);
    if (pre_out && threadIdx.x < 16)
        pre_out[(size_t)threadIdx.x * NN + e] =
            fmaf(ALPHA_P, v, (1.0f - ALPHA_P) * vpartner);

    const int o = threadIdx.x << 2;                 // 0..2044 step 4
    const size_t row = (size_t)e * NN + o;

    // Hoisted per-thread coefficient vectors:
    //   u_b = A_p * Xpost_b   (potentiation gate)
    //   t_b = A_d * xbar_post_b (depression gate)
    float4 u0, u1, t0, t1;
    {
        const float4 ap   = *(const float4*)(A_p + row);
        const float4 ad   = *(const float4*)(A_d + row);
        const float4 xpo0 = *(const float4*)(Xpost + o);
        const float4 xpo1 = *(const float4*)(Xpost + NN + o);
        const float4 xbp0 = *(const float4*)(xbar_post + o);
        const float4 xbp1 = *(const float4*)(xbar_post + NN + o);
        u0.x = ap.x * xpo0.x; u0.y = ap.y * xpo0.y; u0.z = ap.z * xpo0.z; u0.w = ap.w * xpo0.w;
        u1.x = ap.x * xpo1.x; u1.y = ap.y * xpo1.y; u1.z = ap.z * xpo1.z; u1.w = ap.w * xpo1.w;
        t0.x = ad.x * xbp0.x; t0.y = ad.y * xbp0.y; t0.z = ad.z * xbp0.z; t0.w = ad.w * xbp0.w;
        t1.x = ad.x * xbp1.x; t1.y = ad.y * xbp1.y; t1.z = ad.z * xbp1.z; t1.w = ad.w * xbp1.w;
    }

    // acc_b[o] = sum_d dm_d[o] * (u_b[o]*p_bd - t_b[o]*v_bd)
    float4 acc0 = make_float4(0.f, 0.f, 0.f, 0.f);
    float4 acc1 = acc0;
#pragma unroll
    for (int d = 0; d < DD; d++) {
        const float4 dm = *(const float4*)(dmap + (size_t)d * N2 + row);
        const float p0 = __shfl_sync(0xffffffffu, v, d * 2 + 0);
        const float p1 = __shfl_sync(0xffffffffu, v, d * 2 + 1);
        const float v0 = __shfl_sync(0xffffffffu, v, 16 + d * 2 + 0);
        const float v1 = __shfl_sync(0xffffffffu, v, 16 + d * 2 + 1);

        float4 c;
        c.x = fmaf(u0.x, p0, -(t0.x * v0));
        c.y = fmaf(u0.y, p0, -(t0.y * v0));
        c.z = fmaf(u0.z, p0, -(t0.z * v0));
        c.w = fmaf(u0.w, p0, -(t0.w * v0));
        acc0.x = fmaf(dm.x, c.x, acc0.x);
        acc0.y = fmaf(dm.y, c.y, acc0.y);
        acc0.z = fmaf(dm.z, c.z, acc0.z);
        acc0.w = fmaf(dm.w, c.w, acc0.w);

        c.x = fmaf(u1.x, p1, -(t1.x * v1));
        c.y = fmaf(u1.y, p1, -(t1.y * v1));
        c.z = fmaf(u1.z, p1, -(t1.z * v1));
        c.w = fmaf(u1.w, p1, -(t1.w * v1));
        acc1.x = fmaf(dm.x, c.x, acc1.x);
        acc1.y = fmaf(dm.y, c.y, acc1.y);
        acc1.z = fmaf(dm.z, c.z, acc1.z);
        acc1.w = fmaf(dm.w, c.w, acc1.w);
    }

    // batch 0 epilogue
    {
        const float4 w = *(const float4*)(W + row);
        float4 wn;
        wn.x = fminf(fmaxf(w.x + acc0.x, 0.f), 1.f);
        wn.y = fminf(fmaxf(w.y + acc0.y, 0.f), 1.f);
        wn.z = fminf(fmaxf(w.z + acc0.z, 0.f), 1.f);
        wn.w = fminf(fmaxf(w.w + acc0.w, 0.f), 1.f);
        *(float4*)(W_prev_out + row) = w;
        *(float4*)(W_new_out  + row) = wn;
    }
    // batch 1 epilogue
    {
        const size_t widx = (size_t)N2 + row;
        const float4 w = *(const float4*)(W + widx);
        float4 wn;
        wn.x = fminf(fmaxf(w.x + acc1.x, 0.f), 1.f);
        wn.y = fminf(fmaxf(w.y + acc1.y, 0.f), 1.f);
        wn.z = fminf(fmaxf(w.z + acc1.z, 0.f), 1.f);
        wn.w = fminf(fmaxf(w.w + acc1.w, 0.f), 1.f);
        *(float4*)(W_prev_out + widx) = w;
        *(float4*)(W_new_out  + widx) = wn;
    }

    // Fused post-trace update: block 0 only (B*N = 4096 floats).
    // Reload the small inputs here (cold branch, keeps hot-path regs low).
    if (post_out && e == 0) {
#pragma unroll
        for (int b = 0; b < BB; b++) {
            const float4 xpo = *(const float4*)(Xpost + (size_t)b * NN + o);
            const float4 xbp = *(const float4*)(xbar_post + (size_t)b * NN + o);
            float4 pn;
            pn.x = fmaf(ALPHA_D, xbp.x, (1.0f - ALPHA_D) * xpo.x);
            pn.y = fmaf(ALPHA_D, xbp.y, (1.0f - ALPHA_D) * xpo.y);
            pn.z = fmaf(ALPHA_D, xbp.z, (1.0f - ALPHA_D) * xpo.z);
            pn.w = fmaf(ALPHA_D, xbp.w, (1.0f - ALPHA_D) * xpo.w);
            *(float4*)(post_out + (size_t)b * NN + o) = pn;
        }
    }
}

// Fallback: output is only W_prev (straight copy of W).
__global__ void copy_w(const float* __restrict__ W, float* __restrict__ out, long long n)
{
    const long long i = (long long)blockIdx.x * blockDim.x + threadIdx.x;
    if (i * 4 < n) {
        *(float4*)(out + i * 4) = *(const float4*)(W + i * 4);
    }
}

extern "C" void kernel_launch(void* const* d_in, const int* in_sizes, int n_in,
                              void* d_out, int out_size)
{
    const float* Xd        = (const float*)d_in[0];
    const float* Xpost     = (const float*)d_in[1];
    const float* xbar_pre  = (const float*)d_in[2];
    const float* xbar_post = (const float*)d_in[3];
    const float* W         = (const float*)d_in[4];
    const float* dmap      = (const float*)d_in[5];
    const float* A_p       = (const float*)d_in[6];
    const float* A_d       = (const float*)d_in[7];

    float* out = (float*)d_out;
    const long long total = 2 * BN2 + DBN + BN;  // 16,814,080

    if ((long long)out_size >= total) {
        float* W_prev   = out;
        float* W_new    = out + BN2;
        float* pre_o    = out + 2 * BN2;
        float* post_o   = pre_o + DBN;
        stdp_fused<<<NN, 512>>>(Xd, Xpost, xbar_pre, xbar_post, W, dmap,
                                A_p, A_d, W_prev, W_new, pre_o, post_o);
    } else if ((long long)out_size >= 2 * BN2) {
        stdp_fused<<<NN, 512>>>(Xd, Xpost, xbar_pre, xbar_post, W, dmap,
                                A_p, A_d, out, out + BN2,
                                (float*)nullptr, (float*)nullptr);
    } else {
        copy_w<<<(int)((BN2 / 4 + 255) / 256), 256>>>(W, out, BN2);
    }
}

// round 8
// speedup vs baseline: 1.2761x; 1.2761x over previous
#include <cuda_runtime.h>

// Abbott STDP step, fused persistent kernel (barrier-free). D=8, B=2, N=2048.
// Out = concat(W_prev[B,N,N], W_new[B,N,N], xbar_pre_new[D,B,N], xbar_post_new[B,N])
//
// Measured structure notes (do not regress):
//  - Load dmap INSIDE the d-loop, consume into 4 float4 accumulators
//    (front-loading dm[8] cost +3.8us, R4).
//  - Warp-shfl broadcast of per-row scalars; NO smem, NO __syncthreads (R5).
//  - Keep ~63 regs: per-warp load batching beats occupancy. Forcing 3
//    blocks/SM at 40 regs cost +12.5us (R6).
//  - Persistence is safe ONLY because there are no barriers: R3's persistent
//    loop WITH per-row __syncthreads cost -7% DRAM.

#define DD 8
#define BB 2
#define NN 2048
#define ALPHA_P 0.95f
#define ALPHA_D 0.90f
#define PERSIST_GRID 296   // 2 blocks/SM * 148 SMs

static const long long N2  = (long long)NN * NN;       // 4,194,304
static const long long BN2 = (long long)BB * N2;       // 8,388,608
static const long long DBN = (long long)DD * BB * NN;  // 32,768
static const long long BN  = (long long)BB * NN;       // 4,096

__global__ __launch_bounds__(512, 2) void stdp_fused(
    const float* __restrict__ Xd,        // (D,B,N)
    const float* __restrict__ Xpost,     // (B,N)
    const float* __restrict__ xbar_pre,  // (D,B,N)
    const float* __restrict__ xbar_post, // (B,N)
    const float* __restrict__ W,         // (B,N,N)
    const float* __restrict__ dmap,      // (D,N,N)
    const float* __restrict__ A_p,       // (N,N)
    const float* __restrict__ A_d,       // (N,N)
    float* __restrict__ W_prev_out,
    float* __restrict__ W_new_out,
    float* __restrict__ pre_out,         // (D,B,N) or nullptr
    float* __restrict__ post_out)        // (B,N)   or nullptr
{
    const int lane = threadIdx.x & 31;
    const int o = threadIdx.x << 2;                 // 0..2044 step 4

    for (int e = blockIdx.x; e < NN; e += PERSIST_GRID) {
        // Warp-local broadcast of the 2*D*B=32 per-row scalars:
        // lane l<16 holds xbar_pre[l*NN+e] (l = d*BB+b); lane l>=16 holds Xd.
        const float* sbase = (lane < 16) ? xbar_pre : Xd;
        const float v = __ldg(sbase + (size_t)(lane & 15) * NN + e);

        // Fused pre-trace output: warp 0, lanes 0..15 (one value each).
        const float vpartner = __shfl_xor_sync(0xffffffffu, v, 16);
        if (pre_out && threadIdx.x < 16)
            pre_out[(size_t)threadIdx.x * NN + e] =
                fmaf(ALPHA_P, v, (1.0f - ALPHA_P) * vpartner);

        const size_t row = (size_t)e * NN + o;

        const float4 ap = *(const float4*)(A_p + row);
        const float4 ad = *(const float4*)(A_d + row);

        // Accumulate pot/dep sums for both batches in one sweep over d.
        float4 sp0 = make_float4(0.f, 0.f, 0.f, 0.f);
        float4 sd0 = sp0, sp1 = sp0, sd1 = sp0;
#pragma unroll
        for (int d = 0; d < DD; d++) {
            const float4 dm = *(const float4*)(dmap + (size_t)d * N2 + row);
            const float p0 = __shfl_sync(0xffffffffu, v, d * 2 + 0);
            const float p1 = __shfl_sync(0xffffffffu, v, d * 2 + 1);
            const float v0 = __shfl_sync(0xffffffffu, v, 16 + d * 2 + 0);
            const float v1 = __shfl_sync(0xffffffffu, v, 16 + d * 2 + 1);
            sp0.x = fmaf(p0, dm.x, sp0.x); sp0.y = fmaf(p0, dm.y, sp0.y);
            sp0.z = fmaf(p0, dm.z, sp0.z); sp0.w = fmaf(p0, dm.w, sp0.w);
            sd0.x = fmaf(v0, dm.x, sd0.x); sd0.y = fmaf(v0, dm.y, sd0.y);
            sd0.z = fmaf(v0, dm.z, sd0.z); sd0.w = fmaf(v0, dm.w, sd0.w);
            sp1.x = fmaf(p1, dm.x, sp1.x); sp1.y = fmaf(p1, dm.y, sp1.y);
            sp1.z = fmaf(p1, dm.z, sp1.z); sp1.w = fmaf(p1, dm.w, sp1.w);
            sd1.x = fmaf(v1, dm.x, sd1.x); sd1.y = fmaf(v1, dm.y, sd1.y);
            sd1.z = fmaf(v1, dm.z, sd1.z); sd1.w = fmaf(v1, dm.w, sd1.w);
        }

#pragma unroll
        for (int b = 0; b < BB; b++) {
            const float4 sp = b == 0 ? sp0 : sp1;
            const float4 sd = b == 0 ? sd0 : sd1;

            const size_t widx = (size_t)b * N2 + row;
            const float4 w   = *(const float4*)(W + widx);
            const float4 xpo = *(const float4*)(Xpost + (size_t)b * NN + o);
            const float4 xbp = *(const float4*)(xbar_post + (size_t)b * NN + o);

            float4 wn;
            wn.x = fminf(fmaxf(w.x + xpo.x * sp.x * ap.x - xbp.x * sd.x * ad.x, 0.f), 1.f);
            wn.y = fminf(fmaxf(w.y + xpo.y * sp.y * ap.y - xbp.y * sd.y * ad.y, 0.f), 1.f);
            wn.z = fminf(fmaxf(w.z + xpo.z * sp.z * ap.z - xbp.z * sd.z * ad.z, 0.f), 1.f);
            wn.w = fminf(fmaxf(w.w + xpo.w * sp.w * ap.w - xbp.w * sd.w * ad.w, 0.f), 1.f);

            *(float4*)(W_prev_out + widx) = w;
            *(float4*)(W_new_out  + widx) = wn;

            // Fused post-trace update: block 0, first row only.
            if (post_out && e == 0) {
                float4 pn;
                pn.x = fmaf(ALPHA_D, xbp.x, (1.0f - ALPHA_D) * xpo.x);
                pn.y = fmaf(ALPHA_D, xbp.y, (1.0f - ALPHA_D) * xpo.y);
                pn.z = fmaf(ALPHA_D, xbp.z, (1.0f - ALPHA_D) * xpo.z);
                pn.w = fmaf(ALPHA_D, xbp.w, (1.0f - ALPHA_D) * xpo.w);
                *(float4*)(post_out + (size_t)b * NN + o) = pn;
            }
        }
    }
}

// Fallback: output is only W_prev (straight copy of W).
__global__ void copy_w(const float* __restrict__ W, float* __restrict__ out, long long n)
{
    const long long i = (long long)blockIdx.x * blockDim.x + threadIdx.x;
    if (i * 4 < n) {
        *(float4*)(out + i * 4) = *(const float4*)(W + i * 4);
    }
}

extern "C" void kernel_launch(void* const* d_in, const int* in_sizes, int n_in,
                              void* d_out, int out_size)
{
    const float* Xd        = (const float*)d_in[0];
    const float* Xpost     = (const float*)d_in[1];
    const float* xbar_pre  = (const float*)d_in[2];
    const float* xbar_post = (const float*)d_in[3];
    const float* W         = (const float*)d_in[4];
    const float* dmap      = (const float*)d_in[5];
    const float* A_p       = (const float*)d_in[6];
    const float* A_d       = (const float*)d_in[7];

    float* out = (float*)d_out;
    const long long total = 2 * BN2 + DBN + BN;  // 16,814,080

    if ((long long)out_size >= total) {
        float* W_prev   = out;
        float* W_new    = out + BN2;
        float* pre_o    = out + 2 * BN2;
        float* post_o   = pre_o + DBN;
        stdp_fused<<<PERSIST_GRID, 512>>>(Xd, Xpost, xbar_pre, xbar_post, W, dmap,
                                          A_p, A_d, W_prev, W_new, pre_o, post_o);
    } else if ((long long)out_size >= 2 * BN2) {
        stdp_fused<<<PERSIST_GRID, 512>>>(Xd, Xpost, xbar_pre, xbar_post, W, dmap,
                                          A_p, A_d, out, out + BN2,
                                          (float*)nullptr, (float*)nullptr);
    } else {
        copy_w<<<(int)((BN2 / 4 + 255) / 256), 256>>>(W, out, BN2);
    }
}